// round 17
// baseline (speedup 1.0000x reference)
#include <cuda_runtime.h>
#include <cuda_fp16.h>
#include <cstdint>

#define NNODES  50000
#define HID     128
#define NREL    9
#define NEDGES  600000
#define RNBUCK  (NREL * NNODES)
#define CAP     32
#define WTOT    (3 * NREL * HID * HID)
#define HTOT    (NNODES * HID)                 // 6.4M
#define INITN   HTOT                           // covers WTOT and RNBUCK too

#define MTILE   128
#define NROWPAD 50048                          // 391 * 128
#define GRID_M  (NROWPAD / MTILE)              // 391

#define NSTAGE  3
#define KSLICE  64
#define PIT     72                             // smem row pitch in halves
#define AS_ELE  (MTILE * PIT)
#define AS_BYTES (AS_ELE * 2)
#define NSLICE  (NREL * 2)                     // 18 K-slices of 64

// ---------------- scratch (device globals; no allocation) ----------------
__device__ int    g_counts[RNBUCK];
__device__ int    g_bucket[(size_t)RNBUCK * CAP];                  // 57.6 MB
__device__ __align__(256) __half g_Hh[3][HTOT];                    // fp16 emb/H1/H2
__device__ __align__(256) __half g_Wh[WTOT];                       // W^T fp16: [l][r][n][k]
__device__ __align__(256) __half g_Y[(size_t)NREL * NROWPAD * HID]; // 115 MB fp16

// ---------------- helpers ----------------
__device__ __forceinline__ void mma_f16(float& c0, float& c1, float& c2, float& c3,
                                        uint32_t a0, uint32_t a1, uint32_t a2, uint32_t a3,
                                        uint32_t b0, uint32_t b1) {
    asm volatile(
        "mma.sync.aligned.m16n8k16.row.col.f32.f16.f16.f32 "
        "{%0,%1,%2,%3}, {%4,%5,%6,%7}, {%8,%9}, {%0,%1,%2,%3};\n"
        : "+f"(c0), "+f"(c1), "+f"(c2), "+f"(c3)
        : "r"(a0), "r"(a1), "r"(a2), "r"(a3), "r"(b0), "r"(b1));
}
__device__ __forceinline__ void ldm_x4(uint32_t* r, uint32_t addr) {
    asm volatile("ldmatrix.sync.aligned.m8n8.x4.shared.b16 {%0,%1,%2,%3}, [%4];"
                 : "=r"(r[0]), "=r"(r[1]), "=r"(r[2]), "=r"(r[3]) : "r"(addr));
}
__device__ __forceinline__ void cp16(uint32_t sdst, const void* gsrc) {
    asm volatile("cp.async.cg.shared.global [%0], [%1], 16;\n"
                 :: "r"(sdst), "l"(gsrc) : "memory");
}
__device__ __forceinline__ void cp_commit() {
    asm volatile("cp.async.commit_group;\n" ::: "memory");
}
__device__ __forceinline__ void cp_wait() {      // NSTAGE-1 = 2
    asm volatile("cp.async.wait_group 2;\n" ::: "memory");
}

// ---------------- init: zero counts + fp16 W^T + fp16 emb ----------------
__global__ void k_init(const float* __restrict__ W, const float* __restrict__ emb) {
    int i = blockIdx.x * blockDim.x + threadIdx.x;
    if (i < WTOT) {
        int mat = i >> 14, within = i & 16383;
        int n = within >> 7, k = within & 127;
        g_Wh[i] = __float2half_rn(W[(mat << 14) + k * HID + n]);
    }
    if (i < RNBUCK) g_counts[i] = 0;
    if (i < HTOT)   g_Hh[0][i] = __float2half_rn(emb[i]);
}

// ---------------- bucket scatter ----------------
__global__ void k_bucket(const int* __restrict__ dest, const int* __restrict__ etype,
                         const int* __restrict__ src) {
    int e = blockIdx.x * blockDim.x + threadIdx.x;
    if (e < NEDGES) {
        int key = etype[e] * NNODES + dest[e];
        int pos = atomicAdd(&g_counts[key], 1);
        if (pos < CAP) g_bucket[(size_t)key * CAP + pos] = src[e];
    }
}

// ---------------- gather: one warp per Y row --------------------------------
// grid (NROWPAD/8, 9), 256 threads = 8 warps. Warp w sums the bucket of
// (rel=by, dest=bx*8+w) and stores the fp16 row (scaled by inv_s) to Y.
__global__ void __launch_bounds__(256)
k_gather(const __half* __restrict__ Hin, float inv_s) {
    const int lane = threadIdx.x & 31;
    const int wid  = threadIdx.x >> 5;
    const int r    = blockIdx.y;
    const int d    = blockIdx.x * 8 + wid;

    int cnt = 0;
    int key = 0;
    if (d < NNODES) {
        key = r * NNODES + d;
        cnt = g_counts[key];
        if (cnt > CAP) cnt = CAP;
    }

    // lane-parallel src index read (coalesced within the bucket)
    int sv = 0;
    if (lane < cnt) sv = g_bucket[(size_t)key * CAP + lane];

    float4 acc = make_float4(0.f, 0.f, 0.f, 0.f);
    const int mycol = lane * 4;

    int i = 0;
    while (i < cnt) {
        int nb = cnt - i; if (nb > 4) nb = 4;
        uint2 v[4];
        #pragma unroll
        for (int u = 0; u < 4; u++) {
            if (u < nb) {
                int s = __shfl_sync(0xffffffffu, sv, i + u);
                v[u] = *(const uint2*)(Hin + (size_t)s * HID + mycol);
            }
        }
        #pragma unroll
        for (int u = 0; u < 4; u++) {
            if (u < nb) {
                float2 f0 = __half22float2(*(__half2*)&v[u].x);
                float2 f1 = __half22float2(*(__half2*)&v[u].y);
                acc.x += f0.x; acc.y += f0.y;
                acc.z += f1.x; acc.w += f1.y;
            }
        }
        i += nb;
    }

    __half2 h0 = __floats2half2_rn(acc.x * inv_s, acc.y * inv_s);
    __half2 h1 = __floats2half2_rn(acc.z * inv_s, acc.w * inv_s);
    uint2 o_; o_.x = *(uint32_t*)&h0; o_.y = *(uint32_t*)&h1;
    __half* Yg = g_Y + ((size_t)r * NROWPAD + d) * HID;
    __stcs((uint2*)(Yg + mycol), o_);
}

// ---------------- GEMM: H = relu( s * sum_r Y_r @ W_r + cnt_r * b_r ) -------
// fp16 m16n8k16, fp32 accum, ldmatrix fragment loads, 3-stage cp.async.
// (R15 configuration — verified 64 us/layer.)
struct GSMem {
    __half A[NSTAGE][AS_ELE];
    __half W[NSTAGE][AS_ELE];
    float bias[NREL * HID];
};

__global__ void __launch_bounds__(256, 2)
k_gemm(const __half* __restrict__ Y, const __half* __restrict__ Wt_l,
       const float* __restrict__ Bv, float* __restrict__ HoutF,
       __half* __restrict__ HoutH, int relu, float scale, float out_inv) {
    extern __shared__ __align__(16) char smraw[];
    GSMem* sm = (GSMem*)smraw;

    const int tid  = threadIdx.x;
    const int lane = tid & 31;
    const int wid  = tid >> 5;
    const int base = blockIdx.x * MTILE;

    for (int i = tid; i < NREL * HID; i += 256) sm->bias[i] = Bv[i];

    const uint32_t sA0 = (uint32_t)__cvta_generic_to_shared(&sm->A[0][0]);
    const uint32_t sW0 = (uint32_t)__cvta_generic_to_shared(&sm->W[0][0]);

    #define ISSUE(s_, st_) do { \
        const int r_  = (s_) >> 1; \
        const int ks_ = (s_) & 1; \
        const __half* Ag = Y + ((size_t)r_ * NROWPAD + base) * HID + ks_ * KSLICE; \
        const __half* Wg = Wt_l + ((size_t)r_ << 14) + ks_ * KSLICE; \
        const uint32_t sa = sA0 + (st_) * AS_BYTES; \
        const uint32_t sw = sW0 + (st_) * AS_BYTES; \
        _Pragma("unroll") \
        for (int u = 0; u < 4; u++) { \
            int j = tid + 256 * u; \
            int row = j >> 3, seg = j & 7; \
            cp16(sa + (row * PIT + seg * 8) * 2, Ag + (size_t)row * HID + seg * 8); \
            cp16(sw + (row * PIT + seg * 8) * 2, Wg + (size_t)row * HID + seg * 8); \
        } \
        cp_commit(); \
    } while (0)

    ISSUE(0, 0); ISSUE(1, 1); ISSUE(2, 2);

    const int wm    = wid & 3;
    const int wncol = (wid >> 2) * 64;

    const int rowA = wm * 32 + (lane & 7) + ((lane >> 3) & 1) * 8;
    const int kA   = (lane >> 4) * 8;
    const int rowB = wncol + (lane & 7) + ((lane >> 4) & 1) * 8;
    const int kB   = ((lane >> 3) & 1) * 8;

    float c[2][8][4];
    #pragma unroll
    for (int m2 = 0; m2 < 2; m2++)
        #pragma unroll
        for (int nt = 0; nt < 8; nt++)
            #pragma unroll
            for (int j = 0; j < 4; j++) c[m2][nt][j] = 0.0f;

    for (int s = 0; s < NSLICE; s++) {
        const int st = s % NSTAGE;
        cp_wait();
        __syncthreads();

        const uint32_t aBase = sA0 + st * AS_BYTES + (rowA * PIT + kA) * 2;
        const uint32_t wBase = sW0 + st * AS_BYTES + (rowB * PIT + kB) * 2;

        #pragma unroll
        for (int kk = 0; kk < KSLICE; kk += 16) {
            uint32_t a[2][4];
            ldm_x4(a[0], aBase + kk * 2);
            ldm_x4(a[1], aBase + (16 * PIT + kk) * 2);
            #pragma unroll
            for (int ntp = 0; ntp < 4; ntp++) {
                uint32_t b[4];
                ldm_x4(b, wBase + (ntp * 16 * PIT + kk) * 2);
                const int nt0 = ntp * 2;
                mma_f16(c[0][nt0][0], c[0][nt0][1], c[0][nt0][2], c[0][nt0][3],
                        a[0][0], a[0][1], a[0][2], a[0][3], b[0], b[1]);
                mma_f16(c[1][nt0][0], c[1][nt0][1], c[1][nt0][2], c[1][nt0][3],
                        a[1][0], a[1][1], a[1][2], a[1][3], b[0], b[1]);
                mma_f16(c[0][nt0+1][0], c[0][nt0+1][1], c[0][nt0+1][2], c[0][nt0+1][3],
                        a[0][0], a[0][1], a[0][2], a[0][3], b[2], b[3]);
                mma_f16(c[1][nt0+1][0], c[1][nt0+1][1], c[1][nt0+1][2], c[1][nt0+1][3],
                        a[1][0], a[1][1], a[1][2], a[1][3], b[2], b[3]);
            }
        }
        __syncthreads();
        if (s + NSTAGE < NSLICE) ISSUE(s + NSTAGE, st);
    }
    #undef ISSUE

    // ---- epilogue: rescale, bias via per-row true counts, relu, store ----
    const int g  = lane >> 2;
    const int tg = lane & 3;
    #pragma unroll
    for (int m2 = 0; m2 < 2; m2++) {
        #pragma unroll
        for (int h = 0; h < 2; h++) {
            const int row = wm * 32 + m2 * 16 + h * 8 + g;
            const int d = base + row;
            if (d >= NNODES) continue;
            float cnt[NREL];
            #pragma unroll
            for (int r = 0; r < NREL; r++)
                cnt[r] = (float)g_counts[r * NNODES + d];
            #pragma unroll
            for (int nt = 0; nt < 8; nt++) {
                const int col0 = wncol + nt * 8 + tg * 2;
                float v0 = c[m2][nt][h * 2 + 0] * scale;
                float v1 = c[m2][nt][h * 2 + 1] * scale;
                #pragma unroll
                for (int r = 0; r < NREL; r++) {
                    const float cc = cnt[r];
                    v0 += cc * sm->bias[r * HID + col0];
                    v1 += cc * sm->bias[r * HID + col0 + 1];
                }
                if (relu) { v0 = fmaxf(v0, 0.f); v1 = fmaxf(v1, 0.f); }
                if (HoutH) {
                    __half2 p = __floats2half2_rn(v0 * out_inv, v1 * out_inv);
                    *(__half2*)(HoutH + (size_t)d * HID + col0) = p;
                } else {
                    HoutF[(size_t)d * HID + col0]     = v0;
                    HoutF[(size_t)d * HID + col0 + 1] = v1;
                }
            }
        }
    }
}

// ---------------- launch ----------------------------------------------------
extern "C" void kernel_launch(void* const* d_in, const int* in_sizes, int n_in,
                              void* d_out, int out_size) {
    const int*   eidx  = (const int*)d_in[0];      // [2, NEDGES]: row0=dest, row1=src
    const int*   etype = (const int*)d_in[1];
    const float* emb   = (const float*)d_in[2];
    const float* wts   = (const float*)d_in[3];    // [3, NREL, HID, HID]
    const float* bias  = (const float*)d_in[4];    // [3, NREL, HID]
    float*       out   = (float*)d_out;

    const int* dest = eidx;
    const int* src  = eidx + NEDGES;

    __half* hh = nullptr;
    cudaGetSymbolAddress((void**)&hh, g_Hh);
    __half* hh0 = hh;                      // fp16 emb
    __half* hh1 = hh + (size_t)HTOT;       // H1          (scale 1)
    __half* hh2 = hh + (size_t)2 * HTOT;   // H2 * 2^-11
    __half* wt = nullptr;
    cudaGetSymbolAddress((void**)&wt, g_Wh);
    __half* yb = nullptr;
    cudaGetSymbolAddress((void**)&yb, g_Y);

    k_init<<<(INITN + 255) / 256, 256>>>(wts, emb);
    k_bucket<<<(NEDGES + 255) / 256, 256>>>(dest, etype, src);

    const int smem_sz = (int)sizeof(GSMem);
    static_assert(sizeof(GSMem) <= 113 * 1024, "gemm smem too big for 2 blocks/SM");
    cudaFuncSetAttribute(k_gemm, cudaFuncAttributeMaxDynamicSharedMemorySize, smem_sz);

    const size_t wstride = (size_t)NREL * HID * HID;
    const size_t bstride = (size_t)NREL * HID;
    dim3 ggrid(NROWPAD / 8, NREL);         // one warp per Y row

    // Exact power-of-2 scaling chain (fp16 range safety, worst-case bounds):
    //  L1: Y1 = A1 (<=32*1)            gemm*1      -> H1 fp16 (<=844)
    //  L2: Y2 = A2 * 2^-6 (<=422)      gemm*2^6    -> H2*2^-11 fp16 (<=3e4 bound)
    //  L3: Y3 = A3 * 2^-11 * 2^-5      gemm*2^16   -> fp32 out
    k_gather<<<ggrid, 256>>>(hh0, 1.0f);
    k_gemm<<<GRID_M, 256, smem_sz>>>(yb, wt, bias, nullptr, hh1, 1,
                                     1.0f, 1.0f);
    k_gather<<<ggrid, 256>>>(hh1, 1.0f / 64.0f);
    k_gemm<<<GRID_M, 256, smem_sz>>>(yb, wt + wstride, bias + bstride, nullptr, hh2, 1,
                                     64.0f, 1.0f / 2048.0f);
    k_gather<<<ggrid, 256>>>(hh2, 1.0f / 32.0f);
    k_gemm<<<GRID_M, 256, smem_sz>>>(yb, wt + 2 * wstride, bias + 2 * bstride, out, nullptr, 0,
                                     65536.0f, 1.0f);
}